// round 5
// baseline (speedup 1.0000x reference)
#include <cuda_runtime.h>

// ---------------------------------------------------------------------------
// pcqmPostProcess: fused segment-mean (column-split incoming/outgoing) +
// index rebasing. Output layout (float32, flattened tuple order):
//   [ x_new (N_NODES*D) | edge_new (2*E_LAB) | ptr_new (B+1) | batch_vec (N_NODES) ]
//
// 3-kernel pipeline:
//   scan_kernel   : per-graph exclusive offsets + ptr_new
//   prep_kernel   : per-graph padded bucket lists -> global scratch, meta per
//                   node, edge/batch outputs (all the irregular work)
//   gather_kernel : flat, barrier-free streaming gather-mean (97% of traffic)
// ---------------------------------------------------------------------------

#define MAX_B    2048   // max graphs
#define MAX_LG   1024   // max padded bucket-list length per graph per side
#define MAX_N    128    // max original nodes per graph
#define LIST_CAP MAX_LG // per-graph per-side capacity in global scratch

__device__ int g_node_off[MAX_B];   // exclusive cumsum of org_graph_size
__device__ int g_edge_off[MAX_B];   // exclusive cumsum of edge_label_size
__device__ __align__(16) unsigned short g_lin[MAX_B * LIST_CAP];
__device__ __align__(16) unsigned short g_lou[MAX_B * LIST_CAP];
// meta[node] = { lg_base, abs_start_in, abs_start_ou, cnt_in | cnt_ou<<16 }
__device__ int4 g_meta[MAX_B * MAX_N];

// ---------------------------------------------------------------------------
// Kernel 1: shfl-based dual scan. 1024 threads, 2 elems/thread -> B <= 2048.
// ---------------------------------------------------------------------------
__global__ void scan_kernel(const int* __restrict__ org,
                            const int* __restrict__ elab,
                            int B, float* __restrict__ out, long long ptr_sec) {
    const int tid  = threadIdx.x;
    const int lane = tid & 31;
    const int warp = tid >> 5;
    const int i0 = 2 * tid, i1 = 2 * tid + 1;

    int v0 = (i0 < B) ? org[i0]  : 0;
    int v1 = (i1 < B) ? org[i1]  : 0;
    int e0 = (i0 < B) ? elab[i0] : 0;
    int e1 = (i1 < B) ? elab[i1] : 0;

    int sv = v0 + v1, se = e0 + e1;
#pragma unroll
    for (int off = 1; off < 32; off <<= 1) {
        int t = __shfl_up_sync(0xFFFFFFFFu, sv, off); if (lane >= off) sv += t;
        int u = __shfl_up_sync(0xFFFFFFFFu, se, off); if (lane >= off) se += u;
    }
    __shared__ int wsv[32], wse[32];
    if (lane == 31) { wsv[warp] = sv; wse[warp] = se; }
    __syncthreads();
    if (warp == 0) {
        int a = wsv[lane], b = wse[lane];
#pragma unroll
        for (int off = 1; off < 32; off <<= 1) {
            int t = __shfl_up_sync(0xFFFFFFFFu, a, off); if (lane >= off) a += t;
            int u = __shfl_up_sync(0xFFFFFFFFu, b, off); if (lane >= off) b += u;
        }
        wsv[lane] = a; wse[lane] = b;
    }
    __syncthreads();
    const int basev = (warp > 0) ? wsv[warp - 1] : 0;
    const int basee = (warp > 0) ? wse[warp - 1] : 0;
    const int incl1_v = basev + sv, incl0_v = incl1_v - v1;
    const int incl1_e = basee + se, incl0_e = incl1_e - e1;
    if (i0 < B) {
        g_node_off[i0] = incl0_v - v0;
        g_edge_off[i0] = incl0_e - e0;
        out[ptr_sec + 1 + i0] = (float)incl0_v;
    }
    if (i1 < B) {
        g_node_off[i1] = incl1_v - v1;
        g_edge_off[i1] = incl1_e - e1;
        out[ptr_sec + 1 + i1] = (float)incl1_v;
    }
    if (tid == 0) out[ptr_sec] = 0.0f;
}

// ---------------------------------------------------------------------------
// Kernel 2: one 128-thread block per graph. Builds padded (multiple-of-4,
// 0xFFFF sentinel) bucket lists in smem, dumps to global scratch + per-node
// meta. Also writes batch_vec and rebased edge indices.
// ---------------------------------------------------------------------------
__global__ void prep_kernel(const int* __restrict__ lgidx,   // [N_LG, 2]
                            const int* __restrict__ ptr,     // [B+1]
                            const int* __restrict__ org,     // [B]
                            const int* __restrict__ elab,    // [B]
                            const int* __restrict__ eil,     // [2, E_LAB]
                            float*     __restrict__ out,
                            int E_LAB, long long N_NODES, long long D, int B) {
    __shared__ __align__(8) unsigned short lin [MAX_LG];
    __shared__ __align__(8) unsigned short lou [MAX_LG];
    __shared__ unsigned short i0s [MAX_LG];
    __shared__ unsigned short i1s [MAX_LG];
    __shared__ int cin [MAX_N], cou [MAX_N];
    __shared__ int sin_[MAX_N], sou [MAX_N];
    __shared__ int pin [MAX_N], pou [MAX_N];
    __shared__ int tot_in, tot_ou;

    const int g    = blockIdx.x;
    const int tid  = threadIdx.x;
    const int nt   = blockDim.x;
    const int p0      = ptr[0];
    const int lg_base = ptr[g] - p0;
    const int lg_n    = ptr[g + 1] - ptr[g];
    const int npg     = org[g];
    const int nbase   = g_node_off[g];

    for (int i = tid; i < npg; i += nt) { cin[i] = 0; cou[i] = 0; }
    __syncthreads();
    for (int i = tid; i < lg_n; i += nt) {
        int2 v = ((const int2*)lgidx)[lg_base + i];
        i0s[i] = (unsigned short)v.x;
        i1s[i] = (unsigned short)v.y;
        atomicAdd(&cou[v.x], 1);
        atomicAdd(&cin[v.y], 1);
    }
    __syncthreads();
    if (tid == 0) {
        int a = 0, b = 0;
        for (int n = 0; n < npg; n++) {
            sin_[n] = a; pin[n] = a; a += (cin[n] + 3) & ~3;
            sou [n] = b; pou[n] = b; b += (cou[n] + 3) & ~3;
        }
        tot_in = a; tot_ou = b;
    }
    __syncthreads();
    const int ti = tot_in, to = tot_ou;
    for (int i = tid; i < ti; i += nt) lin[i] = 0xFFFFu;
    for (int i = tid; i < to; i += nt) lou[i] = 0xFFFFu;
    __syncthreads();
    for (int i = tid; i < lg_n; i += nt) {
        int p = atomicAdd(&pou[i0s[i]], 1); lou[p] = (unsigned short)i;
        int q = atomicAdd(&pin[i1s[i]], 1); lin[q] = (unsigned short)i;
    }
    __syncthreads();

    // dump lists + meta to global scratch
    const int lbase = g * LIST_CAP;
    for (int i = tid; i < ti; i += nt) g_lin[lbase + i] = lin[i];
    for (int i = tid; i < to; i += nt) g_lou[lbase + i] = lou[i];
    for (int n = tid; n < npg; n += nt) {
        int4 m;
        m.x = lg_base;
        m.y = lbase + sin_[n];
        m.z = lbase + sou[n];
        m.w = (cin[n] & 0xFFFF) | (cou[n] << 16);
        g_meta[nbase + n] = m;
    }

    // batch_vec + rebased edges + nothing else touches these sections
    const long long edge_sec  = N_NODES * D;
    const long long ptr_sec   = edge_sec + 2LL * E_LAB;
    const long long batch_sec = ptr_sec + (B + 1);
    for (int n = tid; n < npg; n += nt)
        out[batch_sec + nbase + n] = (float)g;

    const int e_base = g_edge_off[g];
    const int e_n    = elab[g];
    for (int j = tid; j < e_n; j += nt) {
        out[edge_sec + e_base + j]         = (float)(eil[e_base + j]         - lg_base);
        out[edge_sec + E_LAB + e_base + j] = (float)(eil[E_LAB + e_base + j] - lg_base);
    }
}

// ---------------------------------------------------------------------------
// Kernel 3: flat streaming gather-mean. One thread per (node, float4-lane)
// output. No smem, no barriers -> max occupancy, pure memory issue.
// ---------------------------------------------------------------------------
__global__ void __launch_bounds__(256)
gather_kernel(const float* __restrict__ x,
              float*       __restrict__ out,
              int Dv, int twoHv, int D, long long total) {
    const long long o = (long long)blockIdx.x * blockDim.x + threadIdx.x;
    if (o >= total) return;
    const int n  = (int)(o / Dv);
    const int dv = (int)(o - (long long)n * Dv);

    const int4 m = g_meta[n];
    const bool use_in = (dv < twoHv);
    const int s = use_in ? m.y : m.z;
    const int c = use_in ? (m.w & 0xFFFF) : ((unsigned)m.w >> 16);
    const unsigned short* lst = use_in ? g_lin : g_lou;
    const int cpad = (c + 3) & ~3;
    const float* xb = x + (size_t)m.x * D + (size_t)dv * 4;

    float ax = 0.f, ay = 0.f, az = 0.f, aw = 0.f;
    for (int k = 0; k < cpad; k += 4) {
        ushort4 iv = *reinterpret_cast<const ushort4*>(lst + s + k);
        if (iv.x != 0xFFFFu) {
            float4 v = __ldcs((const float4*)(xb + (size_t)iv.x * D));
            ax += v.x; ay += v.y; az += v.z; aw += v.w;
        }
        if (iv.y != 0xFFFFu) {
            float4 v = __ldcs((const float4*)(xb + (size_t)iv.y * D));
            ax += v.x; ay += v.y; az += v.z; aw += v.w;
        }
        if (iv.z != 0xFFFFu) {
            float4 v = __ldcs((const float4*)(xb + (size_t)iv.z * D));
            ax += v.x; ay += v.y; az += v.z; aw += v.w;
        }
        if (iv.w != 0xFFFFu) {
            float4 v = __ldcs((const float4*)(xb + (size_t)iv.w * D));
            ax += v.x; ay += v.y; az += v.z; aw += v.w;
        }
    }
    const float inv = (c > 0) ? 1.0f / (float)c : 0.0f;
    float4 r;
    r.x = ax * inv; r.y = ay * inv; r.z = az * inv; r.w = aw * inv;
    __stcs((float4*)(out + (size_t)n * D + (size_t)dv * 4), r);
}

// ---------------------------------------------------------------------------
// Scalar fallback (D not divisible by 4) — monolithic, unpadded lists.
// ---------------------------------------------------------------------------
__global__ void graph_kernel1(const float* __restrict__ x,
                              const int*   __restrict__ lgidx,
                              const int*   __restrict__ ptr,
                              const int*   __restrict__ org,
                              const int*   __restrict__ elab,
                              const int*   __restrict__ eil,
                              float*       __restrict__ out,
                              int D, int HDIM, int E_LAB,
                              long long N_NODES, int B) {
    __shared__ unsigned short lin [MAX_LG];
    __shared__ unsigned short lou [MAX_LG];
    __shared__ unsigned short i0s [MAX_LG];
    __shared__ unsigned short i1s [MAX_LG];
    __shared__ int cin [MAX_N], cou [MAX_N];
    __shared__ int sin_[MAX_N], sou [MAX_N];
    __shared__ int pin [MAX_N], pou [MAX_N];

    const int g    = blockIdx.x;
    const int tid  = threadIdx.x;
    const int nt   = blockDim.x;
    const int p0      = ptr[0];
    const int lg_base = ptr[g] - p0;
    const int lg_n    = ptr[g + 1] - ptr[g];
    const int npg     = org[g];
    const int nbase   = g_node_off[g];

    for (int i = tid; i < npg; i += nt) { cin[i] = 0; cou[i] = 0; }
    __syncthreads();
    for (int i = tid; i < lg_n; i += nt) {
        int2 v = ((const int2*)lgidx)[lg_base + i];
        i0s[i] = (unsigned short)v.x;
        i1s[i] = (unsigned short)v.y;
        atomicAdd(&cou[v.x], 1);
        atomicAdd(&cin[v.y], 1);
    }
    __syncthreads();
    if (tid == 0) {
        int a = 0, b = 0;
        for (int n = 0; n < npg; n++) {
            sin_[n] = a; pin[n] = a; a += cin[n];
            sou [n] = b; pou[n] = b; b += cou[n];
        }
    }
    __syncthreads();
    for (int i = tid; i < lg_n; i += nt) {
        int p = atomicAdd(&pou[i0s[i]], 1); lou[p] = (unsigned short)i;
        int q = atomicAdd(&pin[i1s[i]], 1); lin[q] = (unsigned short)i;
    }
    __syncthreads();

    const int nOut = npg * D;
    const int twoH = 2 * HDIM;
    for (int o = tid; o < nOut; o += nt) {
        int n = o / D;
        int d = o - n * D;
        bool use_in = (d < twoH);
        const unsigned short* lst = use_in ? lin : lou;
        int s = use_in ? sin_[n] : sou[n];
        int c = use_in ? cin [n] : cou[n];
        float acc = 0.f;
        for (int k = 0; k < c; k++)
            acc += x[(size_t)(lg_base + lst[s + k]) * D + d];
        out[(size_t)(nbase + n) * D + d] = (c > 0) ? acc / (float)c : 0.0f;
    }

    const long long edge_sec  = N_NODES * (long long)D;
    const long long ptr_sec   = edge_sec + 2LL * E_LAB;
    const long long batch_sec = ptr_sec + (B + 1);
    for (int n = tid; n < npg; n += nt)
        out[batch_sec + nbase + n] = (float)g;
    const int e_base = g_edge_off[g];
    const int e_n    = elab[g];
    for (int j = tid; j < e_n; j += nt) {
        out[edge_sec + e_base + j]         = (float)(eil[e_base + j]         - lg_base);
        out[edge_sec + E_LAB + e_base + j] = (float)(eil[E_LAB + e_base + j] - lg_base);
    }
}

// ---------------------------------------------------------------------------
extern "C" void kernel_launch(void* const* d_in, const int* in_sizes, int n_in,
                              void* d_out, int out_size) {
    const float* x     = (const float*)d_in[0];
    const int*   lgidx = (const int*)  d_in[1];
    const int*   ptr   = (const int*)  d_in[2];
    const int*   org   = (const int*)  d_in[3];
    const int*   elab  = (const int*)  d_in[4];
    const int*   eil   = (const int*)  d_in[5];
    float*       out   = (float*)d_out;

    const int N_LG  = in_sizes[1] / 2;
    const int D     = in_sizes[0] / N_LG;
    const int B     = in_sizes[3];
    const int E_LAB = in_sizes[5] / 2;
    const int HDIM  = D / 3;
    // out_size = N_NODES*D + 2*E_LAB + (B+1) + N_NODES
    const long long N_NODES =
        ((long long)out_size - 2LL * E_LAB - (B + 1)) / (D + 1);
    const long long ptr_sec = N_NODES * (long long)D + 2LL * E_LAB;

    scan_kernel<<<1, 1024>>>(org, elab, B, out, ptr_sec);

    if ((D % 4 == 0) && ((2 * HDIM) % 4 == 0)) {
        prep_kernel<<<B, 128>>>(lgidx, ptr, org, elab, eil, out,
                                E_LAB, N_NODES, (long long)D, B);
        const int Dv    = D >> 2;
        const int twoHv = (2 * HDIM) >> 2;
        const long long total = N_NODES * Dv;
        const int grid = (int)((total + 255) / 256);
        gather_kernel<<<grid, 256>>>(x, out, Dv, twoHv, D, total);
    } else {
        graph_kernel1<<<B, 512>>>(x, lgidx, ptr, org, elab, eil, out,
                                  D, HDIM, E_LAB, N_NODES, B);
    }
}